// round 2
// baseline (speedup 1.0000x reference)
#include <cuda_runtime.h>
#include <math.h>

#define BSZ 32
#define SEQ 512
#define IDIM 512
#define HDIM 512
#define G4H 2048
#define NCTA_REC 128

#define OUT_HT_ELEMS (BSZ*SEQ*2*HDIM)              // 16777216
#define OUT_HN_OFF   OUT_HT_ELEMS
#define OUT_CN_OFF   (OUT_HT_ELEMS + 2*BSZ*HDIM)   // 16809984
#define OUT_TOTAL    (OUT_CN_OFF + 2*BSZ*HDIM)     // 16842752

// Scratch (allocation-free rule: __device__ globals)
__device__ float   g_G[2][SEQ][BSZ][G4H];   // precomputed x@Wih^T + bias, 256MB
__device__ float   g_h[2][2][BSZ][HDIM];    // [buf][dir][b][k] double-buffered h state
__device__ unsigned g_bar_count;
__device__ unsigned g_bar_gen;

__device__ __forceinline__ void grid_barrier(unsigned nb) {
    __syncthreads();
    if (threadIdx.x == 0) {
        __threadfence();
        volatile unsigned* genp = &g_bar_gen;
        unsigned gen = *genp;
        if (atomicAdd(&g_bar_count, 1u) == nb - 1u) {
            g_bar_count = 0u;
            __threadfence();
            *genp = gen + 1u;
        } else {
            while (*genp == gen) { __nanosleep(32); }
        }
        __threadfence();
    }
    __syncthreads();
}

__device__ __forceinline__ float sigm(float x) { return 1.0f / (1.0f + expf(-x)); }

// ---------------------------------------------------------------------------
// Kernel 1: input-projection GEMM.  C[m][n] = sum_k X[m][k]*Wih[n][k] + bias[n]
// m = b*SEQ + t (X is [B,S,I] row-major).  Writes g_G[dir][t][b][n].
// 64x64 tile, TK=16, 256 threads, 4x4 register tile, k-major smem (float4 reads)
// grid: (2048/64, 16384/64, 2 dirs)
// ---------------------------------------------------------------------------
__global__ void __launch_bounds__(256) ih_gemm_kernel(
    const float* __restrict__ X,
    const float* __restrict__ Wih_f, const float* __restrict__ bih_f, const float* __restrict__ bhh_f,
    const float* __restrict__ Wih_b, const float* __restrict__ bih_b, const float* __restrict__ bhh_b)
{
    __shared__ float Xs[16][68];
    __shared__ float Ws[16][68];

    const int dir = blockIdx.z;
    const float* __restrict__ W   = dir ? Wih_b : Wih_f;
    const float* __restrict__ bih = dir ? bih_b : bih_f;
    const float* __restrict__ bhh = dir ? bhh_b : bhh_f;

    const int tid = threadIdx.x;
    const int tx = tid & 15;          // 0..15 -> n
    const int ty = tid >> 4;          // 0..15 -> m
    const int n0 = blockIdx.x * 64;
    const int m0 = blockIdx.y * 64;
    const int lrow = tid >> 2;        // 0..63
    const int lkq  = (tid & 3) * 4;   // 0,4,8,12

    float acc[4][4];
    #pragma unroll
    for (int i = 0; i < 4; i++)
        #pragma unroll
        for (int j = 0; j < 4; j++) acc[i][j] = 0.0f;

    const float* Xp = X + (size_t)(m0 + lrow) * IDIM + lkq;
    const float* Wp = W + (size_t)(n0 + lrow) * IDIM + lkq;

    for (int k0 = 0; k0 < IDIM; k0 += 16) {
        float4 xv = *(const float4*)(Xp + k0);
        float4 wv = *(const float4*)(Wp + k0);
        Xs[lkq + 0][lrow] = xv.x; Xs[lkq + 1][lrow] = xv.y;
        Xs[lkq + 2][lrow] = xv.z; Xs[lkq + 3][lrow] = xv.w;
        Ws[lkq + 0][lrow] = wv.x; Ws[lkq + 1][lrow] = wv.y;
        Ws[lkq + 2][lrow] = wv.z; Ws[lkq + 3][lrow] = wv.w;
        __syncthreads();
        #pragma unroll
        for (int kk = 0; kk < 16; kk++) {
            float4 av = *(const float4*)&Xs[kk][ty * 4];
            float4 bv = *(const float4*)&Ws[kk][tx * 4];
            float a0 = av.x, a1 = av.y, a2 = av.z, a3 = av.w;
            float b0 = bv.x, b1 = bv.y, b2 = bv.z, b3 = bv.w;
            acc[0][0] = fmaf(a0, b0, acc[0][0]); acc[0][1] = fmaf(a0, b1, acc[0][1]);
            acc[0][2] = fmaf(a0, b2, acc[0][2]); acc[0][3] = fmaf(a0, b3, acc[0][3]);
            acc[1][0] = fmaf(a1, b0, acc[1][0]); acc[1][1] = fmaf(a1, b1, acc[1][1]);
            acc[1][2] = fmaf(a1, b2, acc[1][2]); acc[1][3] = fmaf(a1, b3, acc[1][3]);
            acc[2][0] = fmaf(a2, b0, acc[2][0]); acc[2][1] = fmaf(a2, b1, acc[2][1]);
            acc[2][2] = fmaf(a2, b2, acc[2][2]); acc[2][3] = fmaf(a2, b3, acc[2][3]);
            acc[3][0] = fmaf(a3, b0, acc[3][0]); acc[3][1] = fmaf(a3, b1, acc[3][1]);
            acc[3][2] = fmaf(a3, b2, acc[3][2]); acc[3][3] = fmaf(a3, b3, acc[3][3]);
        }
        __syncthreads();
    }

    const int n = n0 + tx * 4;
    float4 bias4;
    bias4.x = bih[n + 0] + bhh[n + 0];
    bias4.y = bih[n + 1] + bhh[n + 1];
    bias4.z = bih[n + 2] + bhh[n + 2];
    bias4.w = bih[n + 3] + bhh[n + 3];

    float* Gout = &g_G[dir][0][0][0];
    #pragma unroll
    for (int mi = 0; mi < 4; mi++) {
        int m = m0 + ty * 4 + mi;
        int b = m >> 9;        // SEQ = 512
        int t = m & 511;
        float4 o;
        o.x = acc[mi][0] + bias4.x;
        o.y = acc[mi][1] + bias4.y;
        o.z = acc[mi][2] + bias4.z;
        o.w = acc[mi][3] + bias4.w;
        *(float4*)(Gout + ((size_t)(t * BSZ + b) << 11) + n) = o;
    }
}

// ---------------------------------------------------------------------------
// Kernel 2: persistent recurrence. 128 CTAs x 256 threads, all co-resident.
// CTA c: dir = c/64, owns hidden units j0..j0+7 (j0 = (c%64)*8) -> 32 gate rows.
// Thread (r_local = tid>>3, kc = tid&7): row = gate*512 + j0 + jj, k-range kc*64..+63.
// Whh slice lives in registers (16 float4) for the whole kernel.
// ---------------------------------------------------------------------------
__global__ void __launch_bounds__(256) rec_kernel(
    const float* __restrict__ Whh_f, const float* __restrict__ Whh_b,
    float* __restrict__ out, int out_size)
{
    __shared__ float hs[16 * HDIM];      // half of h (b-halves), 32KB
    __shared__ float gsm[32][33];        // [r_local][b], padded
    __shared__ float csm[8][32];         // [jj][b] cell state, persistent

    const int tid = threadIdx.x;
    const int cta = blockIdx.x;
    const int dir = cta >> 6;
    const int j0  = (cta & 63) * 8;
    const int r_local = tid >> 3;        // 0..31
    const int kc = tid & 7;              // 0..7
    const int gate = r_local >> 3;       // 0..3 (i,f,g,o)
    const int jj = r_local & 7;          // 0..7
    const int row = gate * HDIM + j0 + jj;
    const int k0 = kc * 64;

    const float* __restrict__ Whh = dir ? Whh_b : Whh_f;

    float4 w4[16];
    #pragma unroll
    for (int i = 0; i < 16; i++)
        w4[i] = *(const float4*)(Whh + (size_t)row * HDIM + k0 + 4 * i);

    // zero h state (both buffers, both dirs): 65536 floats over 32768 threads
    {
        float* hp = &g_h[0][0][0][0];
        int base = (cta * 256 + tid) * 2;
        hp[base] = 0.0f; hp[base + 1] = 0.0f;
    }
    ((float*)csm)[tid] = 0.0f;

    grid_barrier(NCTA_REC);

    const bool write_tail = (out_size >= OUT_TOTAL);

    for (int s = 0; s < SEQ; s++) {
        const int t = dir ? (SEQ - 1 - s) : s;
        const int cur = s & 1, nxt = cur ^ 1;

        // preload input-projection tile: g_G[dir][t][b][rows] -> gsm[r][b]
        {
            int bb = tid >> 3;              // 0..31
            int r0 = (tid & 7) * 4;         // 0,4,..,28
            int gg = r0 >> 3;
            int j4 = r0 & 7;                // 0 or 4
            float4 gv = *(const float4*)&g_G[dir][t][bb][gg * HDIM + j0 + j4];
            gsm[r0 + 0][bb] = gv.x;
            gsm[r0 + 1][bb] = gv.y;
            gsm[r0 + 2][bb] = gv.z;
            gsm[r0 + 3][bb] = gv.w;
        }

        #pragma unroll
        for (int half = 0; half < 2; half++) {
            // load 16 batch-rows of h into smem
            {
                const float4* src = (const float4*)(&g_h[cur][dir][half * 16][0]);
                float4* dst = (float4*)hs;
                #pragma unroll
                for (int i = 0; i < 8; i++)
                    dst[tid + 256 * i] = src[tid + 256 * i];
            }
            __syncthreads();

            #pragma unroll 1
            for (int bl = 0; bl < 16; bl++) {
                const int b = half * 16 + bl;
                const float4* hp = (const float4*)&hs[bl * HDIM + k0];
                float p0 = 0.f, p1 = 0.f, p2 = 0.f, p3 = 0.f;
                #pragma unroll
                for (int i = 0; i < 16; i++) {
                    float4 hv = hp[i];
                    p0 = fmaf(hv.x, w4[i].x, p0);
                    p1 = fmaf(hv.y, w4[i].y, p1);
                    p2 = fmaf(hv.z, w4[i].z, p2);
                    p3 = fmaf(hv.w, w4[i].w, p3);
                }
                float p = (p0 + p1) + (p2 + p3);
                p += __shfl_xor_sync(0xffffffffu, p, 1);
                p += __shfl_xor_sync(0xffffffffu, p, 2);
                p += __shfl_xor_sync(0xffffffffu, p, 4);
                if (kc == 0) gsm[r_local][b] += p;
            }
            __syncthreads();
        }

        // elementwise gates: thread -> (jj = tid&7, b = tid>>3)
        {
            const int ej = tid & 7;
            const int eb = tid >> 3;
            float ig = gsm[0 * 8 + ej][eb];
            float fg = gsm[1 * 8 + ej][eb];
            float gg = gsm[2 * 8 + ej][eb];
            float og = gsm[3 * 8 + ej][eb];
            float c = csm[ej][eb];
            c = sigm(fg) * c + sigm(ig) * tanhf(gg);
            float h = sigm(og) * tanhf(c);
            csm[ej][eb] = c;
            g_h[nxt][dir][eb][j0 + ej] = h;
            out[(size_t)(eb * SEQ + t) * (2 * HDIM) + dir * HDIM + j0 + ej] = h;
            if (s == SEQ - 1 && write_tail) {
                out[OUT_HN_OFF + dir * (BSZ * HDIM) + eb * HDIM + j0 + ej] = h;
                out[OUT_CN_OFF + dir * (BSZ * HDIM) + eb * HDIM + j0 + ej] = c;
            }
        }

        grid_barrier(NCTA_REC);
    }
}

extern "C" void kernel_launch(void* const* d_in, const int* in_sizes, int n_in,
                              void* d_out, int out_size) {
    const float* X     = (const float*)d_in[0];
    const float* Wih_f = (const float*)d_in[1];
    const float* Whh_f = (const float*)d_in[2];
    const float* bih_f = (const float*)d_in[3];
    const float* bhh_f = (const float*)d_in[4];
    const float* Wih_b = (const float*)d_in[5];
    const float* Whh_b = (const float*)d_in[6];
    const float* bih_b = (const float*)d_in[7];
    const float* bhh_b = (const float*)d_in[8];
    float* out = (float*)d_out;

    dim3 g1(G4H / 64, (BSZ * SEQ) / 64, 2);
    ih_gemm_kernel<<<g1, 256>>>(X, Wih_f, bih_f, bhh_f, Wih_b, bih_b, bhh_b);
    rec_kernel<<<NCTA_REC, 256>>>(Whh_f, Whh_b, out, out_size);
}

// round 3
// speedup vs baseline: 5.0751x; 5.0751x over previous
#include <cuda_runtime.h>
#include <math.h>

#define BSZ 32
#define SEQ 512
#define IDIM 512
#define HDIM 512
#define G4H 2048

#define OUT_HT_ELEMS (BSZ*SEQ*2*HDIM)              // 16777216
#define OUT_HN_OFF   OUT_HT_ELEMS
#define OUT_CN_OFF   (OUT_HT_ELEMS + 2*BSZ*HDIM)   // 16809984
#define OUT_TOTAL    (OUT_CN_OFF + 2*BSZ*HDIM)     // 16842752

// Scratch (allocation-free rule: __device__ globals)
__device__ float    g_G[2][SEQ][BSZ][G4H];   // precomputed x@Wih^T + bias, 256MB
__device__ float    g_h[2][2][BSZ][HDIM];    // [buf][dir][b][k] double-buffered h state
__device__ unsigned g_bar_count[2];
__device__ unsigned g_bar_gen[2];

__device__ __forceinline__ void dir_barrier(int dir) {
    __syncthreads();
    if (threadIdx.x == 0) {
        __threadfence();
        volatile unsigned* genp = &g_bar_gen[dir];
        unsigned gen = *genp;
        if (atomicAdd(&g_bar_count[dir], 1u) == 63u) {
            g_bar_count[dir] = 0u;
            __threadfence();
            *genp = gen + 1u;
        } else {
            while (*genp == gen) { }
        }
        __threadfence();
    }
    __syncthreads();
}

__device__ __forceinline__ void fma2(unsigned long long& acc,
                                     unsigned long long a, unsigned long long b) {
    asm("fma.rn.f32x2 %0, %1, %2, %0;" : "+l"(acc) : "l"(a), "l"(b));
}
__device__ __forceinline__ float red2(unsigned long long v) {
    float lo, hi;
    asm("mov.b64 {%0, %1}, %2;" : "=f"(lo), "=f"(hi) : "l"(v));
    return lo + hi;
}
__device__ __forceinline__ float sigm(float x) { return 1.0f / (1.0f + expf(-x)); }

// ---------------------------------------------------------------------------
// Kernel 1: input-projection GEMM.  C[m][n] = sum_k X[m][k]*Wih[n][k] + bias[n]
// (unchanged from R2 — FFMA bound ~1.9ms; recurrence was the bottleneck)
// ---------------------------------------------------------------------------
__global__ void __launch_bounds__(256) ih_gemm_kernel(
    const float* __restrict__ X,
    const float* __restrict__ Wih_f, const float* __restrict__ bih_f, const float* __restrict__ bhh_f,
    const float* __restrict__ Wih_b, const float* __restrict__ bih_b, const float* __restrict__ bhh_b)
{
    __shared__ float Xs[16][68];
    __shared__ float Ws[16][68];

    const int dir = blockIdx.z;
    const float* __restrict__ W   = dir ? Wih_b : Wih_f;
    const float* __restrict__ bih = dir ? bih_b : bih_f;
    const float* __restrict__ bhh = dir ? bhh_b : bhh_f;

    const int tid = threadIdx.x;
    const int tx = tid & 15;
    const int ty = tid >> 4;
    const int n0 = blockIdx.x * 64;
    const int m0 = blockIdx.y * 64;
    const int lrow = tid >> 2;
    const int lkq  = (tid & 3) * 4;

    float acc[4][4];
    #pragma unroll
    for (int i = 0; i < 4; i++)
        #pragma unroll
        for (int j = 0; j < 4; j++) acc[i][j] = 0.0f;

    const float* Xp = X + (size_t)(m0 + lrow) * IDIM + lkq;
    const float* Wp = W + (size_t)(n0 + lrow) * IDIM + lkq;

    for (int k0 = 0; k0 < IDIM; k0 += 16) {
        float4 xv = *(const float4*)(Xp + k0);
        float4 wv = *(const float4*)(Wp + k0);
        Xs[lkq + 0][lrow] = xv.x; Xs[lkq + 1][lrow] = xv.y;
        Xs[lkq + 2][lrow] = xv.z; Xs[lkq + 3][lrow] = xv.w;
        Ws[lkq + 0][lrow] = wv.x; Ws[lkq + 1][lrow] = wv.y;
        Ws[lkq + 2][lrow] = wv.z; Ws[lkq + 3][lrow] = wv.w;
        __syncthreads();
        #pragma unroll
        for (int kk = 0; kk < 16; kk++) {
            float4 av = *(const float4*)&Xs[kk][ty * 4];
            float4 bv = *(const float4*)&Ws[kk][tx * 4];
            float a0 = av.x, a1 = av.y, a2 = av.z, a3 = av.w;
            float b0 = bv.x, b1 = bv.y, b2 = bv.z, b3 = bv.w;
            acc[0][0] = fmaf(a0, b0, acc[0][0]); acc[0][1] = fmaf(a0, b1, acc[0][1]);
            acc[0][2] = fmaf(a0, b2, acc[0][2]); acc[0][3] = fmaf(a0, b3, acc[0][3]);
            acc[1][0] = fmaf(a1, b0, acc[1][0]); acc[1][1] = fmaf(a1, b1, acc[1][1]);
            acc[1][2] = fmaf(a1, b2, acc[1][2]); acc[1][3] = fmaf(a1, b3, acc[1][3]);
            acc[2][0] = fmaf(a2, b0, acc[2][0]); acc[2][1] = fmaf(a2, b1, acc[2][1]);
            acc[2][2] = fmaf(a2, b2, acc[2][2]); acc[2][3] = fmaf(a2, b3, acc[2][3]);
            acc[3][0] = fmaf(a3, b0, acc[3][0]); acc[3][1] = fmaf(a3, b1, acc[3][1]);
            acc[3][2] = fmaf(a3, b2, acc[3][2]); acc[3][3] = fmaf(a3, b3, acc[3][3]);
        }
        __syncthreads();
    }

    const int n = n0 + tx * 4;
    float4 bias4;
    bias4.x = bih[n + 0] + bhh[n + 0];
    bias4.y = bih[n + 1] + bhh[n + 1];
    bias4.z = bih[n + 2] + bhh[n + 2];
    bias4.w = bih[n + 3] + bhh[n + 3];

    float* Gout = &g_G[dir][0][0][0];
    #pragma unroll
    for (int mi = 0; mi < 4; mi++) {
        int m = m0 + ty * 4 + mi;
        int b = m >> 9;
        int t = m & 511;
        float4 o;
        o.x = acc[mi][0] + bias4.x;
        o.y = acc[mi][1] + bias4.y;
        o.z = acc[mi][2] + bias4.z;
        o.w = acc[mi][3] + bias4.w;
        *(float4*)(Gout + ((size_t)(t * BSZ + b) << 11) + n) = o;
    }
}

// ---------------------------------------------------------------------------
// Kernel 2: persistent recurrence, v2.
// 128 CTAs x 256 threads. CTA c: dir=c>>6, owns 8 hidden units (32 gate rows).
// Thread: lane = kc in 0..31 (16 k-values each), warp rq owns rows 4rq..4rq+3.
// Swizzled k-chunk reads (conflict-free), packed f32x2 FMAs, 6-shfl reduction.
// ---------------------------------------------------------------------------
__global__ void __launch_bounds__(256) rec_kernel(
    const float* __restrict__ Whh_f, const float* __restrict__ Whh_b,
    float* __restrict__ out, int out_size)
{
    extern __shared__ float hs[];        // 32*512 floats = 64KB (dynamic)
    __shared__ float gsm[32][33];        // [row][b] gate pre-activations
    __shared__ float csm[8][36];         // [jj][b] cell state (padded: conflict-free)

    const int tid  = threadIdx.x;
    const int cta  = blockIdx.x;
    const int dir  = cta >> 6;
    const int cd   = cta & 63;
    const int j0   = cd * 8;
    const int lane = tid & 31;           // kc: k-chunk 16 floats
    const int rq   = tid >> 5;           // warp id -> rows 4rq..4rq+3
    const int q    = (lane >> 1) & 3;    // bank-deswizzle rotation
    const int kbase = lane * 16;

    const float* __restrict__ Whh = dir ? Whh_b : Whh_f;

    int off[4];
    #pragma unroll
    for (int j = 0; j < 4; j++) off[j] = (j + q) & 3;

    // Load 4 rows x 16 k of Whh into packed u64 registers, in swizzled k order
    unsigned long long w2[4][8];
    #pragma unroll
    for (int r = 0; r < 4; r++) {
        int r_local = 4 * rq + r;
        int gate = r_local >> 3;
        int jj   = r_local & 7;
        const ulonglong2* wrow =
            (const ulonglong2*)(Whh + (size_t)(gate * HDIM + j0 + jj) * HDIM + kbase);
        #pragma unroll
        for (int j = 0; j < 4; j++) {
            ulonglong2 wv = wrow[off[j]];
            w2[r][2 * j]     = wv.x;
            w2[r][2 * j + 1] = wv.y;
        }
    }

    // zero this direction's initial h slice (16384 floats over 64 CTAs x 256 thr)
    (&g_h[0][dir][0][0])[cd * 256 + tid] = 0.0f;
    for (int i = tid; i < 8 * 36; i += 256) ((float*)csm)[i] = 0.0f;

    // preload first step's input projection into gsm
    {
        int t0 = dir ? (SEQ - 1) : 0;
        int bb = tid >> 3;
        int r0 = (tid & 7) * 4;
        int gg = r0 >> 3;
        int j4 = r0 & 7;
        float4 gv = *(const float4*)&g_G[dir][t0][bb][gg * HDIM + j0 + j4];
        gsm[r0 + 0][bb] = gv.x; gsm[r0 + 1][bb] = gv.y;
        gsm[r0 + 2][bb] = gv.z; gsm[r0 + 3][bb] = gv.w;
    }

    dir_barrier(dir);   // h zero-init visible across the direction

    const bool write_tail = (out_size >= OUT_TOTAL);
    const int  r_red  = 4 * rq + ((lane >> 4) & 1) * 2 + ((lane >> 3) & 1);
    const bool writer = ((lane & 7) == 0);
    const bool hi16 = (lane & 16) != 0;
    const bool hi8  = (lane & 8)  != 0;

    for (int s = 0; s < SEQ; s++) {
        const int cur = s & 1, nxt = cur ^ 1;

        // stage full h[32][512] into smem (64KB)
        {
            const float4* src = (const float4*)&g_h[cur][dir][0][0];
            float4* dst = (float4*)hs;
            #pragma unroll
            for (int i = 0; i < 16; i++)
                dst[tid + 256 * i] = src[tid + 256 * i];
        }
        __syncthreads();

        const float* hrow = hs + kbase;
        #pragma unroll 1
        for (int bl = 0; bl < BSZ; bl++) {
            const ulonglong2* hp = (const ulonglong2*)(hrow + bl * HDIM);
            unsigned long long ha[8];
            #pragma unroll
            for (int j = 0; j < 4; j++) {
                ulonglong2 hv = hp[off[j]];       // swizzled: conflict-free
                ha[2 * j]     = hv.x;
                ha[2 * j + 1] = hv.y;
            }
            unsigned long long a0 = 0, a1 = 0, a2 = 0, a3 = 0;
            #pragma unroll
            for (int j = 0; j < 8; j++) {
                fma2(a0, ha[j], w2[0][j]);
                fma2(a1, ha[j], w2[1][j]);
                fma2(a2, ha[j], w2[2][j]);
                fma2(a3, ha[j], w2[3][j]);
            }
            float s0 = red2(a0), s1 = red2(a1), s2 = red2(a2), s3 = red2(a3);
            // fold 16: low lanes -> rows +0/+1, high lanes -> rows +2/+3
            float t0 = hi16 ? s0 : s2;
            float p0 = (hi16 ? s2 : s0) + __shfl_xor_sync(0xffffffffu, t0, 16);
            float t1 = hi16 ? s1 : s3;
            float p1 = (hi16 ? s3 : s1) + __shfl_xor_sync(0xffffffffu, t1, 16);
            // fold 8: bit3=0 keeps p0 (row +0), bit3=1 keeps p1 (row +1)
            float t2 = hi8 ? p0 : p1;
            float v  = (hi8 ? p1 : p0) + __shfl_xor_sync(0xffffffffu, t2, 8);
            v += __shfl_xor_sync(0xffffffffu, v, 4);
            v += __shfl_xor_sync(0xffffffffu, v, 2);
            v += __shfl_xor_sync(0xffffffffu, v, 1);
            if (writer) gsm[r_red][bl] += v;      // one writer per (row,b)
        }
        __syncthreads();

        // elementwise gates: thread -> (jj = tid&7, b = tid>>3)
        {
            const int ej = tid & 7;
            const int eb = tid >> 3;
            float ig = gsm[ej][eb];
            float fg = gsm[8 + ej][eb];
            float gg = gsm[16 + ej][eb];
            float og = gsm[24 + ej][eb];
            float c = csm[ej][eb];
            c = sigm(fg) * c + sigm(ig) * tanhf(gg);
            float h = sigm(og) * tanhf(c);
            csm[ej][eb] = c;
            const int t = dir ? (SEQ - 1 - s) : s;
            g_h[nxt][dir][eb][j0 + ej] = h;
            out[(size_t)(eb * SEQ + t) * (2 * HDIM) + dir * HDIM + j0 + ej] = h;
            if (s == SEQ - 1 && write_tail) {
                out[OUT_HN_OFF + dir * (BSZ * HDIM) + eb * HDIM + j0 + ej] = h;
                out[OUT_CN_OFF + dir * (BSZ * HDIM) + eb * HDIM + j0 + ej] = c;
            }
        }
        __syncthreads();

        // preload next step's G (overlaps with the barrier wait)
        if (s + 1 < SEQ) {
            int tn = dir ? (SEQ - 2 - s) : (s + 1);
            int bb = tid >> 3;
            int r0 = (tid & 7) * 4;
            int gg = r0 >> 3;
            int j4 = r0 & 7;
            float4 gv = *(const float4*)&g_G[dir][tn][bb][gg * HDIM + j0 + j4];
            gsm[r0 + 0][bb] = gv.x; gsm[r0 + 1][bb] = gv.y;
            gsm[r0 + 2][bb] = gv.z; gsm[r0 + 3][bb] = gv.w;
        }

        dir_barrier(dir);
    }
}

extern "C" void kernel_launch(void* const* d_in, const int* in_sizes, int n_in,
                              void* d_out, int out_size) {
    const float* X     = (const float*)d_in[0];
    const float* Wih_f = (const float*)d_in[1];
    const float* Whh_f = (const float*)d_in[2];
    const float* bih_f = (const float*)d_in[3];
    const float* bhh_f = (const float*)d_in[4];
    const float* Wih_b = (const float*)d_in[5];
    const float* Whh_b = (const float*)d_in[6];
    const float* bih_b = (const float*)d_in[7];
    const float* bhh_b = (const float*)d_in[8];
    float* out = (float*)d_out;

    cudaFuncSetAttribute(rec_kernel, cudaFuncAttributeMaxDynamicSharedMemorySize,
                         32 * HDIM * (int)sizeof(float));

    dim3 g1(G4H / 64, (BSZ * SEQ) / 64, 2);
    ih_gemm_kernel<<<g1, 256>>>(X, Wih_f, bih_f, bhh_f, Wih_b, bih_b, bhh_b);
    rec_kernel<<<128, 256, 32 * HDIM * sizeof(float)>>>(Whh_f, Whh_b, out, out_size);
}

// round 4
// speedup vs baseline: 5.7632x; 1.1356x over previous
#include <cuda_runtime.h>
#include <math.h>

#define BSZ 32
#define SEQ 512
#define IDIM 512
#define HDIM 512
#define G4H 2048

#define OUT_HT_ELEMS (BSZ*SEQ*2*HDIM)              // 16777216
#define OUT_HN_OFF   OUT_HT_ELEMS
#define OUT_CN_OFF   (OUT_HT_ELEMS + 2*BSZ*HDIM)   // 16809984
#define OUT_TOTAL    (OUT_CN_OFF + 2*BSZ*HDIM)     // 16842752

// Scratch (allocation-free rule: __device__ globals)
__device__ float    g_G[2][SEQ][BSZ][G4H];   // precomputed x@Wih^T + bias, 256MB
__device__ float    g_h[2][2][BSZ][HDIM];    // [buf][dir][b][k] double-buffered h state
__device__ unsigned g_bar_count[2];
__device__ unsigned g_bar_gen[2];

__device__ __forceinline__ void dir_barrier(int dir) {
    __syncthreads();
    if (threadIdx.x == 0) {
        __threadfence();
        volatile unsigned* genp = &g_bar_gen[dir];
        unsigned gen = *genp;
        if (atomicAdd(&g_bar_count[dir], 1u) == 63u) {
            g_bar_count[dir] = 0u;
            __threadfence();
            *genp = gen + 1u;
        } else {
            while (*genp == gen) { }
        }
        __threadfence();
    }
    __syncthreads();
}

__device__ __forceinline__ void fma2(unsigned long long& acc,
                                     unsigned long long a, unsigned long long b) {
    asm("fma.rn.f32x2 %0, %1, %2, %0;" : "+l"(acc) : "l"(a), "l"(b));
}
__device__ __forceinline__ float red2(unsigned long long v) {
    float lo, hi;
    asm("mov.b64 {%0, %1}, %2;" : "=f"(lo), "=f"(hi) : "l"(v));
    return lo + hi;
}
__device__ __forceinline__ unsigned long long dup2(float x) {
    unsigned long long r;
    asm("mov.b64 %0, {%1, %1};" : "=l"(r) : "f"(x));
    return r;
}
__device__ __forceinline__ float2 upk2(unsigned long long v) {
    float2 r;
    asm("mov.b64 {%0, %1}, %2;" : "=f"(r.x), "=f"(r.y) : "l"(v));
    return r;
}
__device__ __forceinline__ float sigm(float x) { return 1.0f / (1.0f + expf(-x)); }

// ---------------------------------------------------------------------------
// Kernel 1: input-projection GEMM with packed f32x2 FMAs.
// C[m][n] = sum_k X[m][k]*Wih[n][k] + bias[n];  m = b*SEQ + t.
// 64x64 tile, TK=16, 256 threads, 4x4 register tile held as 4x2 u64 pairs.
// Ws row stride = 68 floats = 272B = 17*16B -> u64x2 loads stay 16B aligned.
// ---------------------------------------------------------------------------
__global__ void __launch_bounds__(256) ih_gemm_kernel(
    const float* __restrict__ X,
    const float* __restrict__ Wih_f, const float* __restrict__ bih_f, const float* __restrict__ bhh_f,
    const float* __restrict__ Wih_b, const float* __restrict__ bih_b, const float* __restrict__ bhh_b)
{
    __shared__ float Xs[16][68];
    __shared__ float Ws[16][68];

    const int dir = blockIdx.z;
    const float* __restrict__ W   = dir ? Wih_b : Wih_f;
    const float* __restrict__ bih = dir ? bih_b : bih_f;
    const float* __restrict__ bhh = dir ? bhh_b : bhh_f;

    const int tid = threadIdx.x;
    const int tx = tid & 15;
    const int ty = tid >> 4;
    const int n0 = blockIdx.x * 64;
    const int m0 = blockIdx.y * 64;
    const int lrow = tid >> 2;
    const int lkq  = (tid & 3) * 4;

    unsigned long long acc2[4][2];
    #pragma unroll
    for (int i = 0; i < 4; i++) { acc2[i][0] = 0ull; acc2[i][1] = 0ull; }

    const float* Xp = X + (size_t)(m0 + lrow) * IDIM + lkq;
    const float* Wp = W + (size_t)(n0 + lrow) * IDIM + lkq;

    for (int k0 = 0; k0 < IDIM; k0 += 16) {
        float4 xv = *(const float4*)(Xp + k0);
        float4 wv = *(const float4*)(Wp + k0);
        Xs[lkq + 0][lrow] = xv.x; Xs[lkq + 1][lrow] = xv.y;
        Xs[lkq + 2][lrow] = xv.z; Xs[lkq + 3][lrow] = xv.w;
        Ws[lkq + 0][lrow] = wv.x; Ws[lkq + 1][lrow] = wv.y;
        Ws[lkq + 2][lrow] = wv.z; Ws[lkq + 3][lrow] = wv.w;
        __syncthreads();
        #pragma unroll
        for (int kk = 0; kk < 16; kk++) {
            float4 av = *(const float4*)&Xs[kk][ty * 4];
            ulonglong2 bp = *(const ulonglong2*)&Ws[kk][tx * 4];   // (b0,b1),(b2,b3)
            unsigned long long d0 = dup2(av.x);
            unsigned long long d1 = dup2(av.y);
            unsigned long long d2 = dup2(av.z);
            unsigned long long d3 = dup2(av.w);
            fma2(acc2[0][0], d0, bp.x); fma2(acc2[0][1], d0, bp.y);
            fma2(acc2[1][0], d1, bp.x); fma2(acc2[1][1], d1, bp.y);
            fma2(acc2[2][0], d2, bp.x); fma2(acc2[2][1], d2, bp.y);
            fma2(acc2[3][0], d3, bp.x); fma2(acc2[3][1], d3, bp.y);
        }
        __syncthreads();
    }

    const int n = n0 + tx * 4;
    float4 bias4;
    bias4.x = bih[n + 0] + bhh[n + 0];
    bias4.y = bih[n + 1] + bhh[n + 1];
    bias4.z = bih[n + 2] + bhh[n + 2];
    bias4.w = bih[n + 3] + bhh[n + 3];

    float* Gout = &g_G[dir][0][0][0];
    #pragma unroll
    for (int mi = 0; mi < 4; mi++) {
        int m = m0 + ty * 4 + mi;
        int b = m >> 9;
        int t = m & 511;
        float2 u0 = upk2(acc2[mi][0]);
        float2 u1 = upk2(acc2[mi][1]);
        float4 o;
        o.x = u0.x + bias4.x;
        o.y = u0.y + bias4.y;
        o.z = u1.x + bias4.z;
        o.w = u1.y + bias4.w;
        *(float4*)(Gout + ((size_t)(t * BSZ + b) << 11) + n) = o;
    }
}

// ---------------------------------------------------------------------------
// Kernel 2: persistent recurrence, v3.
// 128 CTAs x 512 threads. CTA c: dir=c>>6, owns 8 hidden units (32 gate rows).
// Batch split across warp-halves: warps 0-7 -> b 0..15, warps 8-15 -> b 16..31.
// Warp (w&7)=rq owns rows 4rq..4rq+3; lane owns k-chunk of 16 (swizzled).
// Packed f32x2 FMAs, 6-shfl folded reduction, bl-loop unrolled x2 to overlap
// shfl chains with next iteration's LDS/FMA.
// ---------------------------------------------------------------------------
__global__ void __launch_bounds__(512) rec_kernel(
    const float* __restrict__ Whh_f, const float* __restrict__ Whh_b,
    float* __restrict__ out, int out_size)
{
    extern __shared__ float hs[];        // 32*512 floats = 64KB (dynamic)
    __shared__ float gsm[32][33];        // [row][b] gate pre-activations
    __shared__ float csm[8][36];         // [jj][b] cell state (padded)

    const int tid  = threadIdx.x;
    const int cta  = blockIdx.x;
    const int dir  = cta >> 6;
    const int cd   = cta & 63;
    const int j0   = cd * 8;
    const int lane = tid & 31;
    const int warp = tid >> 5;           // 0..15
    const int rq   = warp & 7;           // rows 4rq..4rq+3
    const int bh   = warp >> 3;          // batch half: 0 -> b 0..15, 1 -> b 16..31
    const int q    = (lane >> 1) & 3;
    const int kbase = lane * 16;

    const float* __restrict__ Whh = dir ? Whh_b : Whh_f;

    int off[4];
    #pragma unroll
    for (int j = 0; j < 4; j++) off[j] = (j + q) & 3;

    // Load 4 rows x 16 k of Whh into packed u64 registers, swizzled k order
    unsigned long long w2[4][8];
    #pragma unroll
    for (int r = 0; r < 4; r++) {
        int r_local = 4 * rq + r;
        int gate = r_local >> 3;
        int jj   = r_local & 7;
        const ulonglong2* wrow =
            (const ulonglong2*)(Whh + (size_t)(gate * HDIM + j0 + jj) * HDIM + kbase);
        #pragma unroll
        for (int j = 0; j < 4; j++) {
            ulonglong2 wv = wrow[off[j]];
            w2[r][2 * j]     = wv.x;
            w2[r][2 * j + 1] = wv.y;
        }
    }

    // zero this direction's initial h slice + cell state
    if (tid < 256) (&g_h[0][dir][0][0])[cd * 256 + tid] = 0.0f;
    for (int i = tid; i < 8 * 36; i += 512) ((float*)csm)[i] = 0.0f;

    // preload first step's input projection into gsm
    if (tid < 256) {
        int t0 = dir ? (SEQ - 1) : 0;
        int bb = tid >> 3;
        int r0 = (tid & 7) * 4;
        int gg = r0 >> 3;
        int j4 = r0 & 7;
        float4 gv = *(const float4*)&g_G[dir][t0][bb][gg * HDIM + j0 + j4];
        gsm[r0 + 0][bb] = gv.x; gsm[r0 + 1][bb] = gv.y;
        gsm[r0 + 2][bb] = gv.z; gsm[r0 + 3][bb] = gv.w;
    }

    dir_barrier(dir);   // h zero-init visible across the direction

    const bool write_tail = (out_size >= OUT_TOTAL);
    const int  r_red  = 4 * rq + ((lane >> 4) & 1) * 2 + ((lane >> 3) & 1);
    const bool writer = ((lane & 7) == 0);
    const bool hi16 = (lane & 16) != 0;
    const bool hi8  = (lane & 8)  != 0;

    for (int s = 0; s < SEQ; s++) {
        const int cur = s & 1, nxt = cur ^ 1;

        // stage full h[32][512] into smem (64KB, 8 float4 per thread)
        {
            const float4* src = (const float4*)&g_h[cur][dir][0][0];
            float4* dst = (float4*)hs;
            #pragma unroll
            for (int i = 0; i < 8; i++)
                dst[tid + 512 * i] = src[tid + 512 * i];
        }
        __syncthreads();

        const float* hrow = hs + kbase + bh * (16 * HDIM);
        #pragma unroll 2
        for (int bl = 0; bl < 16; bl++) {
            const int b = bh * 16 + bl;
            const ulonglong2* hp = (const ulonglong2*)(hrow + bl * HDIM);
            unsigned long long ha[8];
            #pragma unroll
            for (int j = 0; j < 4; j++) {
                ulonglong2 hv = hp[off[j]];       // swizzled: conflict-free
                ha[2 * j]     = hv.x;
                ha[2 * j + 1] = hv.y;
            }
            unsigned long long a0 = 0, a1 = 0, a2 = 0, a3 = 0;
            #pragma unroll
            for (int j = 0; j < 8; j++) {
                fma2(a0, ha[j], w2[0][j]);
                fma2(a1, ha[j], w2[1][j]);
                fma2(a2, ha[j], w2[2][j]);
                fma2(a3, ha[j], w2[3][j]);
            }
            float s0 = red2(a0), s1 = red2(a1), s2 = red2(a2), s3 = red2(a3);
            // fold 16: low lanes keep rows +0/+1, high lanes rows +2/+3
            float t0 = hi16 ? s0 : s2;
            float p0 = (hi16 ? s2 : s0) + __shfl_xor_sync(0xffffffffu, t0, 16);
            float t1 = hi16 ? s1 : s3;
            float p1 = (hi16 ? s3 : s1) + __shfl_xor_sync(0xffffffffu, t1, 16);
            // fold 8
            float t2 = hi8 ? p0 : p1;
            float v  = (hi8 ? p1 : p0) + __shfl_xor_sync(0xffffffffu, t2, 8);
            v += __shfl_xor_sync(0xffffffffu, v, 4);
            v += __shfl_xor_sync(0xffffffffu, v, 2);
            v += __shfl_xor_sync(0xffffffffu, v, 1);
            if (writer) gsm[r_red][b] += v;       // one writer per (row,b)
        }
        __syncthreads();

        // elementwise gates: thread -> (jj = tid&7, b = tid>>3)
        if (tid < 256) {
            const int ej = tid & 7;
            const int eb = tid >> 3;
            float ig = gsm[ej][eb];
            float fg = gsm[8 + ej][eb];
            float gg = gsm[16 + ej][eb];
            float og = gsm[24 + ej][eb];
            float c = csm[ej][eb];
            c = sigm(fg) * c + sigm(ig) * tanhf(gg);
            float h = sigm(og) * tanhf(c);
            csm[ej][eb] = c;
            const int t = dir ? (SEQ - 1 - s) : s;
            g_h[nxt][dir][eb][j0 + ej] = h;
            out[(size_t)(eb * SEQ + t) * (2 * HDIM) + dir * HDIM + j0 + ej] = h;
            if (s == SEQ - 1 && write_tail) {
                out[OUT_HN_OFF + dir * (BSZ * HDIM) + eb * HDIM + j0 + ej] = h;
                out[OUT_CN_OFF + dir * (BSZ * HDIM) + eb * HDIM + j0 + ej] = c;
            }
        }
        __syncthreads();

        // preload next step's G (overlaps the barrier wait)
        if (s + 1 < SEQ && tid < 256) {
            int tn = dir ? (SEQ - 2 - s) : (s + 1);
            int bb = tid >> 3;
            int r0 = (tid & 7) * 4;
            int gg = r0 >> 3;
            int j4 = r0 & 7;
            float4 gv = *(const float4*)&g_G[dir][tn][bb][gg * HDIM + j0 + j4];
            gsm[r0 + 0][bb] = gv.x; gsm[r0 + 1][bb] = gv.y;
            gsm[r0 + 2][bb] = gv.z; gsm[r0 + 3][bb] = gv.w;
        }

        dir_barrier(dir);
    }
}

extern "C" void kernel_launch(void* const* d_in, const int* in_sizes, int n_in,
                              void* d_out, int out_size) {
    const float* X     = (const float*)d_in[0];
    const float* Wih_f = (const float*)d_in[1];
    const float* Whh_f = (const float*)d_in[2];
    const float* bih_f = (const float*)d_in[3];
    const float* bhh_f = (const float*)d_in[4];
    const float* Wih_b = (const float*)d_in[5];
    const float* Whh_b = (const float*)d_in[6];
    const float* bih_b = (const float*)d_in[7];
    const float* bhh_b = (const float*)d_in[8];
    float* out = (float*)d_out;

    cudaFuncSetAttribute(rec_kernel, cudaFuncAttributeMaxDynamicSharedMemorySize,
                         32 * HDIM * (int)sizeof(float));

    dim3 g1(G4H / 64, (BSZ * SEQ) / 64, 2);
    ih_gemm_kernel<<<g1, 256>>>(X, Wih_f, bih_f, bhh_f, Wih_b, bih_b, bhh_b);
    rec_kernel<<<128, 512, 32 * HDIM * sizeof(float)>>>(Whh_f, Whh_b, out, out_size);
}